// round 1
// baseline (speedup 1.0000x reference)
#include <cuda_runtime.h>
#include <cstdint>
#include <cstddef>

#define NN    8192      // nodes (M and K of big GEMM)
#define NCOL  768       // 24 times * 32 out feats
#define BM    128
#define BN    128
#define BK    32
#define PAD_A 36        // floats per A smem row (conflict-free frag loads)
#define PAD_B 136       // floats per B smem row

// scratch (static device globals: allocation-free per harness rules)
__device__ float g_Z[(size_t)NN * NCOL];
__device__ float g_invdeg[NN];

// ---------------------------------------------------------------------------
// Kernel 1: inv_deg[i] = 1 / (1 + sum_j adj[i][j])
// ---------------------------------------------------------------------------
__global__ void deg_kernel(const float* __restrict__ adj) {
    __shared__ float red[256];
    const int row = blockIdx.x;
    const float4* p = reinterpret_cast<const float4*>(adj + (size_t)row * NN);
    float s = 0.f;
#pragma unroll
    for (int i = 0; i < (NN / 4) / 256; i++) {
        float4 v = p[threadIdx.x + i * 256];
        s += (v.x + v.y) + (v.z + v.w);
    }
    red[threadIdx.x] = s;
    __syncthreads();
    for (int off = 128; off > 0; off >>= 1) {
        if (threadIdx.x < off) red[threadIdx.x] += red[threadIdx.x + off];
        __syncthreads();
    }
    if (threadIdx.x == 0) g_invdeg[row] = 1.0f / (red[0] + 1.0f);
}

// ---------------------------------------------------------------------------
// Kernel 2: Z = X @ W    (per node: [24,32] @ [32,32] -> [24,32])
// ---------------------------------------------------------------------------
__global__ void xw_kernel(const float* __restrict__ X, const float* __restrict__ W) {
    __shared__ float Ws[32][33];
    __shared__ float Xs[24][32];
    const int node = blockIdx.x;
    const int tid = threadIdx.x;  // 256
    for (int i = tid; i < 1024; i += 256) Ws[i >> 5][i & 31] = W[i];
    for (int i = tid; i < NCOL; i += 256) Xs[i >> 5][i & 31] = X[(size_t)node * NCOL + i];
    __syncthreads();
    const int o  = tid & 31;
    const int t0 = tid >> 5;
#pragma unroll
    for (int r = 0; r < 3; r++) {
        const int t = t0 + r * 8;
        float acc = 0.f;
#pragma unroll
        for (int a = 0; a < 32; a++) acc += Xs[t][a] * Ws[a][o];
        g_Z[(size_t)node * NCOL + t * 32 + o] = acc;
    }
}

// ---------------------------------------------------------------------------
// Kernel 3: big GEMM  out = (adj @ Z + Z_self) * inv_deg + bias
// CTA tile 128x128, K-chunks of 32, cp.async double-buffered,
// mma.sync.m16n8k8 tf32 (fp32 accumulate).
// ---------------------------------------------------------------------------
__device__ __forceinline__ void cp16(uint32_t smem_addr, const void* gptr) {
    asm volatile("cp.async.cg.shared.global [%0], [%1], 16;\n"
                 :: "r"(smem_addr), "l"(gptr));
}

__global__ void __launch_bounds__(256, 2)
gemm_kernel(const float* __restrict__ A, const float* __restrict__ bias,
            float* __restrict__ out) {
    extern __shared__ float smem[];
    float* As = smem;                       // [2][BM][PAD_A]
    float* Bs = smem + 2 * BM * PAD_A;      // [2][BK][PAD_B]
    __shared__ float biasS[32];

    const int tid = threadIdx.x;
    const int m0 = blockIdx.y * BM;
    const int n0 = blockIdx.x * BN;

    if (tid < 32) biasS[tid] = bias[tid];

    // global->smem load mapping (all 16B aligned, fully in-bounds)
    const int am = tid >> 3;           // 0..31 (A row group, +32*i)
    const int ak = (tid & 7) << 2;     // 0,4,...,28
    const int bk = tid >> 5;           // 0..7  (B row group, +8*i)
    const int bn = (tid & 31) << 2;    // 0,4,...,124

    const uint32_t sA = (uint32_t)__cvta_generic_to_shared(As);
    const uint32_t sB = (uint32_t)__cvta_generic_to_shared(Bs);

    auto load_chunk = [&](int kc, int buf) {
        const float* Ag = A + (size_t)(m0 + am) * NN + kc * BK + ak;
        uint32_t Ad = sA + (uint32_t)(buf * BM * PAD_A + am * PAD_A + ak) * 4u;
#pragma unroll
        for (int i = 0; i < 4; i++)
            cp16(Ad + (uint32_t)(i * 32 * PAD_A) * 4u, Ag + (size_t)i * 32 * NN);
        const float* Bg = g_Z + (size_t)(kc * BK + bk) * NCOL + n0 + bn;
        uint32_t Bd = sB + (uint32_t)(buf * BK * PAD_B + bk * PAD_B + bn) * 4u;
#pragma unroll
        for (int i = 0; i < 4; i++)
            cp16(Bd + (uint32_t)(i * 8 * PAD_B) * 4u, Bg + (size_t)i * 8 * NCOL);
        asm volatile("cp.async.commit_group;\n" ::);
    };

    float acc[4][4][4];
#pragma unroll
    for (int mi = 0; mi < 4; mi++)
#pragma unroll
        for (int ni = 0; ni < 4; ni++)
#pragma unroll
            for (int c = 0; c < 4; c++) acc[mi][ni][c] = 0.f;

    const int lane = tid & 31;
    const int warp = tid >> 5;
    const int wm = (warp >> 2) * 64;   // warp M offset (2 rows of warps)
    const int wn = (warp & 3) * 32;    // warp N offset (4 cols of warps)
    const int lr = lane >> 2;          // 0..7
    const int lc = lane & 3;           // 0..3

    load_chunk(0, 0);

    const int NKC = NN / BK;  // 256
    for (int kc = 0; kc < NKC; kc++) {
        const int buf = kc & 1;
        if (kc + 1 < NKC) {
            load_chunk(kc + 1, buf ^ 1);
            asm volatile("cp.async.wait_group 1;\n" ::);
        } else {
            asm volatile("cp.async.wait_group 0;\n" ::);
        }
        __syncthreads();

        const float* Ab = As + buf * BM * PAD_A;
        const float* Bb = Bs + buf * BK * PAD_B;
#pragma unroll
        for (int s = 0; s < 4; s++) {
            const int kb = s * 8;
            uint32_t bf[4][2];
#pragma unroll
            for (int ni = 0; ni < 4; ni++) {
                bf[ni][0] = __float_as_uint(Bb[(kb + lc) * PAD_B + wn + ni * 8 + lr]);
                bf[ni][1] = __float_as_uint(Bb[(kb + 4 + lc) * PAD_B + wn + ni * 8 + lr]);
            }
#pragma unroll
            for (int mi = 0; mi < 4; mi++) {
                const int r = wm + mi * 16 + lr;
                const uint32_t a0 = __float_as_uint(Ab[r * PAD_A + kb + lc]);
                const uint32_t a1 = __float_as_uint(Ab[(r + 8) * PAD_A + kb + lc]);
                const uint32_t a2 = __float_as_uint(Ab[r * PAD_A + kb + 4 + lc]);
                const uint32_t a3 = __float_as_uint(Ab[(r + 8) * PAD_A + kb + 4 + lc]);
#pragma unroll
                for (int ni = 0; ni < 4; ni++) {
                    asm volatile(
                        "mma.sync.aligned.m16n8k8.row.col.f32.tf32.tf32.f32 "
                        "{%0,%1,%2,%3}, {%4,%5,%6,%7}, {%8,%9}, {%0,%1,%2,%3};\n"
                        : "+f"(acc[mi][ni][0]), "+f"(acc[mi][ni][1]),
                          "+f"(acc[mi][ni][2]), "+f"(acc[mi][ni][3])
                        : "r"(a0), "r"(a1), "r"(a2), "r"(a3),
                          "r"(bf[ni][0]), "r"(bf[ni][1]));
                }
            }
        }
        __syncthreads();
    }

    // epilogue: (+ self-loop Z, * inv_deg, + bias)
#pragma unroll
    for (int mi = 0; mi < 4; mi++) {
        const int row0 = m0 + wm + mi * 16 + lr;
        const int row1 = row0 + 8;
        const float id0 = g_invdeg[row0];
        const float id1 = g_invdeg[row1];
#pragma unroll
        for (int ni = 0; ni < 4; ni++) {
            const int col = n0 + wn + ni * 8 + lc * 2;
            const float b0v = biasS[col & 31];
            const float b1v = biasS[(col + 1) & 31];
            const float2 z0 = *reinterpret_cast<const float2*>(&g_Z[(size_t)row0 * NCOL + col]);
            const float2 z1 = *reinterpret_cast<const float2*>(&g_Z[(size_t)row1 * NCOL + col]);
            float2 o0, o1;
            o0.x = (acc[mi][ni][0] + z0.x) * id0 + b0v;
            o0.y = (acc[mi][ni][1] + z0.y) * id0 + b1v;
            o1.x = (acc[mi][ni][2] + z1.x) * id1 + b0v;
            o1.y = (acc[mi][ni][3] + z1.y) * id1 + b1v;
            *reinterpret_cast<float2*>(&out[(size_t)row0 * NCOL + col]) = o0;
            *reinterpret_cast<float2*>(&out[(size_t)row1 * NCOL + col]) = o1;
        }
    }
}

// ---------------------------------------------------------------------------
extern "C" void kernel_launch(void* const* d_in, const int* in_sizes, int n_in,
                              void* d_out, int out_size) {
    const float* X    = (const float*)d_in[0];   // node_feats [8192,24,32]
    const float* adj  = (const float*)d_in[1];   // adj_matrix [8192,8192]
    const float* W    = (const float*)d_in[2];   // weight [32,32]
    const float* bias = (const float*)d_in[3];   // bias [32]
    float* out = (float*)d_out;

    const int smem_bytes = 2 * (BM * PAD_A + BK * PAD_B) * 4;  // 71680
    cudaFuncSetAttribute(gemm_kernel, cudaFuncAttributeMaxDynamicSharedMemorySize,
                         smem_bytes);

    deg_kernel<<<NN, 256>>>(adj);
    xw_kernel<<<NN, 256>>>(X, W);
    gemm_kernel<<<dim3(NCOL / BN, NN / BM), 256, smem_bytes>>>(adj, bias, out);
}

// round 3
// speedup vs baseline: 1.8036x; 1.8036x over previous
#include <cuda_runtime.h>
#include <cuda_fp16.h>
#include <cstdint>
#include <cstddef>

#define NN    8192
#define NCOL  768
#define BM    128
#define BN    192
#define BK    64
#define THREADS 384
#define STAGES 3
#define A_STAGE_BYTES (BM * BK * 2)                  // 16384
#define B_STAGE_BYTES (BN * BK * 2)                  // 24576
#define STAGE_BYTES   (A_STAGE_BYTES + B_STAGE_BYTES) // 40960
#define SMEM_BYTES    (STAGES * STAGE_BYTES)          // 122880

// scratch (static device globals: allocation-free per harness rules)
__device__ __half g_Ah [(size_t)NN * NN];     // fp16 adjacency (row-major = K-major)
__device__ float  g_Z  [(size_t)NN * NCOL];   // Z = X@W fp32 (for epilogue self-loop)
__device__ __half g_ZTh[(size_t)NCOL * NN];   // Z^T fp16 (K-major B operand)
__device__ float  g_invdeg[NN];

// ---------------------------------------------------------------------------
// helpers
// ---------------------------------------------------------------------------
__device__ __forceinline__ uint32_t swz128(uint32_t o) { return o ^ ((o >> 3) & 0x70); }

__device__ __forceinline__ void cp16(uint32_t smem_addr, const void* gptr) {
    asm volatile("cp.async.cg.shared.global [%0], [%1], 16;\n"
                 :: "r"(smem_addr), "l"(gptr));
}

__device__ __forceinline__ void ldm_x4(uint32_t& r0, uint32_t& r1, uint32_t& r2,
                                       uint32_t& r3, uint32_t addr) {
    asm volatile("ldmatrix.sync.aligned.m8n8.x4.shared.b16 {%0,%1,%2,%3}, [%4];"
                 : "=r"(r0), "=r"(r1), "=r"(r2), "=r"(r3) : "r"(addr));
}

__device__ __forceinline__ void mma_fp16(float* c, const uint32_t* a, const uint32_t* b) {
    asm volatile(
        "mma.sync.aligned.m16n8k16.row.col.f32.f16.f16.f32 "
        "{%0,%1,%2,%3}, {%4,%5,%6,%7}, {%8,%9}, {%0,%1,%2,%3};\n"
        : "+f"(c[0]), "+f"(c[1]), "+f"(c[2]), "+f"(c[3])
        : "r"(a[0]), "r"(a[1]), "r"(a[2]), "r"(a[3]), "r"(b[0]), "r"(b[1]));
}

// ---------------------------------------------------------------------------
// Kernel 1: fused  inv_deg[i] = 1/(1 + sum_j adj[i][j])  AND  A_half = fp16(adj)
// ---------------------------------------------------------------------------
__global__ void degconv_kernel(const float* __restrict__ adj) {
    __shared__ float red[256];
    const int row = blockIdx.x;
    const float4* p = reinterpret_cast<const float4*>(adj + (size_t)row * NN);
    uint2* o = reinterpret_cast<uint2*>(g_Ah + (size_t)row * NN);
    float s = 0.f;
#pragma unroll
    for (int i = 0; i < (NN / 4) / 256; i++) {
        const int idx = threadIdx.x + i * 256;
        float4 v = p[idx];
        s += (v.x + v.y) + (v.z + v.w);
        __half2 h0 = __floats2half2_rn(v.x, v.y);
        __half2 h1 = __floats2half2_rn(v.z, v.w);
        uint2 u;
        u.x = *reinterpret_cast<const unsigned*>(&h0);
        u.y = *reinterpret_cast<const unsigned*>(&h1);
        o[idx] = u;
    }
    red[threadIdx.x] = s;
    __syncthreads();
    for (int off = 128; off > 0; off >>= 1) {
        if (threadIdx.x < off) red[threadIdx.x] += red[threadIdx.x + off];
        __syncthreads();
    }
    if (threadIdx.x == 0) g_invdeg[row] = 1.0f / (red[0] + 1.0f);
}

// ---------------------------------------------------------------------------
// Kernel 2: Z = X @ W   (row-major fp32 [8192, 768])
// ---------------------------------------------------------------------------
__global__ void xw_kernel(const float* __restrict__ X, const float* __restrict__ W) {
    __shared__ float Ws[32][33];
    __shared__ float Xs[24][32];
    const int node = blockIdx.x;
    const int tid = threadIdx.x;  // 256
    for (int i = tid; i < 1024; i += 256) Ws[i >> 5][i & 31] = W[i];
    for (int i = tid; i < NCOL; i += 256) Xs[i >> 5][i & 31] = X[(size_t)node * NCOL + i];
    __syncthreads();
    const int o  = tid & 31;
    const int t0 = tid >> 5;
#pragma unroll
    for (int r = 0; r < 3; r++) {
        const int t = t0 + r * 8;
        float acc = 0.f;
#pragma unroll
        for (int a = 0; a < 32; a++) acc += Xs[t][a] * Ws[a][o];
        g_Z[(size_t)node * NCOL + t * 32 + o] = acc;
    }
}

// ---------------------------------------------------------------------------
// Kernel 2b: ZTh = fp16(Z^T)   [768, 8192], K-major B operand
// ---------------------------------------------------------------------------
__global__ void transconv_kernel() {
    __shared__ float s[32][33];
    const int r0 = blockIdx.x * 32;   // node tile
    const int c0 = blockIdx.y * 32;   // feature-col tile
    const int x = threadIdx.x;        // 0..31
    const int y = threadIdx.y;        // 0..7
#pragma unroll
    for (int i = 0; i < 4; i++) {
        const int yy = y + i * 8;
        s[yy][x] = g_Z[(size_t)(r0 + yy) * NCOL + c0 + x];
    }
    __syncthreads();
#pragma unroll
    for (int i = 0; i < 4; i++) {
        const int yy = y + i * 8;
        g_ZTh[(size_t)(c0 + yy) * NN + r0 + x] = __float2half(s[x][yy]);
    }
}

// ---------------------------------------------------------------------------
// Kernel 3: fp16 tensor GEMM   out = (adj @ Z + Z_self) * inv_deg + bias
// CTA tile 128x192, BK=64, 3-stage cp.async, ldmatrix + mma.m16n8k16
// 384 threads = 12 warps as 2x6, warp tile 64x32.
// ---------------------------------------------------------------------------
__global__ void __launch_bounds__(THREADS, 1)
gemm_kernel(const float* __restrict__ bias, float* __restrict__ out) {
    extern __shared__ char smem[];
    __shared__ float biasS[32];

    const int tid  = threadIdx.x;
    const int lane = tid & 31;
    const int warp = tid >> 5;
    const int m0 = blockIdx.y * BM;
    const int n0 = blockIdx.x * BN;

    if (tid < 32) biasS[tid] = bias[tid];

    const uint32_t sbase = (uint32_t)__cvta_generic_to_shared(smem);

    // ---- stage loader: 2560 x 16B chunks (A: 1024, B: 1536) ----
    auto load_stage = [&](int kc, int st) {
        const uint32_t Ad = sbase + st * STAGE_BYTES;
        const uint32_t Bd = Ad + A_STAGE_BYTES;
        const __half* Ag = g_Ah  + (size_t)m0 * NN + (size_t)kc * BK;
        const __half* Bg = g_ZTh + (size_t)n0 * NN + (size_t)kc * BK;
#pragma unroll
        for (int i = tid; i < 2560; i += THREADS) {
            if (i < 1024) {
                const int r = i >> 3, c = i & 7;
                cp16(Ad + swz128((uint32_t)(r * 128 + c * 16)),
                     Ag + (size_t)r * NN + c * 8);
            } else {
                const int j = i - 1024;
                const int n = j >> 3, c = j & 7;
                cp16(Bd + swz128((uint32_t)(n * 128 + c * 16)),
                     Bg + (size_t)n * NN + c * 8);
            }
        }
        asm volatile("cp.async.commit_group;\n" ::);
    };

    float acc[4][4][4];
#pragma unroll
    for (int mi = 0; mi < 4; mi++)
#pragma unroll
        for (int ni = 0; ni < 4; ni++)
#pragma unroll
            for (int c = 0; c < 4; c++) acc[mi][ni][c] = 0.f;

    const int wm = (warp / 6) * 64;   // warp M offset
    const int wn = (warp % 6) * 32;   // warp N offset

    const int NKC = NN / BK;  // 128
    load_stage(0, 0);
    load_stage(1, 1);

    for (int kc = 0; kc < NKC; kc++) {
        const int st = kc % STAGES;
        if (kc + 2 < NKC) {
            load_stage(kc + 2, (kc + 2) % STAGES);
            asm volatile("cp.async.wait_group 2;\n" ::);
        } else if (kc + 1 < NKC) {
            asm volatile("cp.async.wait_group 1;\n" ::);
        } else {
            asm volatile("cp.async.wait_group 0;\n" ::);
        }
        __syncthreads();

        const uint32_t Ab = sbase + st * STAGE_BYTES;
        const uint32_t Bb = Ab + A_STAGE_BYTES;
#pragma unroll
        for (int s = 0; s < 4; s++) {        // k16 steps within BK=64
            uint32_t a[4][4];
#pragma unroll
            for (int mi = 0; mi < 4; mi++) {
                const int row = wm + mi * 16 + (lane & 15);
                const uint32_t off = (uint32_t)(row * 128 + s * 32 + (lane >> 4) * 16);
                ldm_x4(a[mi][0], a[mi][1], a[mi][2], a[mi][3], Ab + swz128(off));
            }
            uint32_t b[4][2];
#pragma unroll
            for (int nj = 0; nj < 2; nj++) {
                const int row = wn + nj * 16 + (lane >> 4) * 8 + (lane & 7);
                const uint32_t off = (uint32_t)(row * 128 + s * 32 + ((lane >> 3) & 1) * 16);
                ldm_x4(b[nj * 2][0], b[nj * 2][1], b[nj * 2 + 1][0], b[nj * 2 + 1][1],
                       Bb + swz128(off));
            }
#pragma unroll
            for (int mi = 0; mi < 4; mi++)
#pragma unroll
                for (int ni = 0; ni < 4; ni++)
                    mma_fp16(acc[mi][ni], a[mi], b[ni]);
        }
        __syncthreads();
    }

    // ---- epilogue: (+ self-loop Z) * inv_deg + bias ----
    const int lr = lane >> 2;   // 0..7  (row within m8 group)
    const int lc = lane & 3;    // 0..3  (col pair)
#pragma unroll
    for (int mi = 0; mi < 4; mi++) {
        const int row0 = m0 + wm + mi * 16 + lr;
        const int row1 = row0 + 8;
        const float id0 = g_invdeg[row0];
        const float id1 = g_invdeg[row1];
#pragma unroll
        for (int ni = 0; ni < 4; ni++) {
            const int col = n0 + wn + ni * 8 + lc * 2;
            const float b0v = biasS[col & 31];
            const float b1v = biasS[(col + 1) & 31];
            const float2 z0 = *reinterpret_cast<const float2*>(&g_Z[(size_t)row0 * NCOL + col]);
            const float2 z1 = *reinterpret_cast<const float2*>(&g_Z[(size_t)row1 * NCOL + col]);
            float2 o0, o1;
            o0.x = (acc[mi][ni][0] + z0.x) * id0 + b0v;
            o0.y = (acc[mi][ni][1] + z0.y) * id0 + b1v;
            o1.x = (acc[mi][ni][2] + z1.x) * id1 + b0v;
            o1.y = (acc[mi][ni][3] + z1.y) * id1 + b1v;
            *reinterpret_cast<float2*>(&out[(size_t)row0 * NCOL + col]) = o0;
            *reinterpret_cast<float2*>(&out[(size_t)row1 * NCOL + col]) = o1;
        }
    }
}

// ---------------------------------------------------------------------------
extern "C" void kernel_launch(void* const* d_in, const int* in_sizes, int n_in,
                              void* d_out, int out_size) {
    const float* X    = (const float*)d_in[0];   // node_feats [8192,24,32]
    const float* adj  = (const float*)d_in[1];   // adj_matrix [8192,8192]
    const float* W    = (const float*)d_in[2];   // weight [32,32]
    const float* bias = (const float*)d_in[3];   // bias [32]
    float* out = (float*)d_out;

    cudaFuncSetAttribute(gemm_kernel, cudaFuncAttributeMaxDynamicSharedMemorySize,
                         SMEM_BYTES);

    degconv_kernel<<<NN, 256>>>(adj);
    xw_kernel<<<NN, 256>>>(X, W);
    transconv_kernel<<<dim3(NN / 32, NCOL / 32), dim3(32, 8)>>>();
    gemm_kernel<<<dim3(NCOL / BN, NN / BM), THREADS, SMEM_BYTES>>>(bias, out);
}

// round 4
// speedup vs baseline: 1.8296x; 1.0144x over previous
#include <cuda_runtime.h>
#include <cuda_fp16.h>
#include <cstdint>
#include <cstddef>

#define NN    8192
#define NCOL  768
#define BM    128
#define BN    192
#define BK    64
#define THREADS 384
#define STAGES 3
#define A_STAGE_BYTES (BM * BK * 2)                  // 16384
#define B_STAGE_BYTES (BN * BK * 2)                  // 24576
#define STAGE_BYTES   (A_STAGE_BYTES + B_STAGE_BYTES) // 40960
#define SMEM_BYTES    (STAGES * STAGE_BYTES)          // 122880

// scratch (static device globals: allocation-free per harness rules)
__device__ __half g_Ah [(size_t)NN * NN];     // fp16 adjacency (row-major = K-major)
__device__ float  g_Z  [(size_t)NN * NCOL];   // Z = X@W fp32 (for epilogue self-loop)
__device__ __half g_ZTh[(size_t)NCOL * NN];   // Z^T fp16 (K-major B operand)
__device__ float  g_invdeg[NN];

// ---------------------------------------------------------------------------
// helpers
// ---------------------------------------------------------------------------
__device__ __forceinline__ uint32_t swz128(uint32_t o) { return o ^ ((o >> 3) & 0x70); }

__device__ __forceinline__ void cp16(uint32_t smem_addr, const void* gptr) {
    asm volatile("cp.async.cg.shared.global [%0], [%1], 16;\n"
                 :: "r"(smem_addr), "l"(gptr));
}

__device__ __forceinline__ void ldm_x4(uint32_t& r0, uint32_t& r1, uint32_t& r2,
                                       uint32_t& r3, uint32_t addr) {
    asm volatile("ldmatrix.sync.aligned.m8n8.x4.shared.b16 {%0,%1,%2,%3}, [%4];"
                 : "=r"(r0), "=r"(r1), "=r"(r2), "=r"(r3) : "r"(addr));
}

__device__ __forceinline__ void mma_fp16(float* c, const uint32_t* a, const uint32_t* b) {
    asm volatile(
        "mma.sync.aligned.m16n8k16.row.col.f32.f16.f16.f32 "
        "{%0,%1,%2,%3}, {%4,%5,%6,%7}, {%8,%9}, {%0,%1,%2,%3};\n"
        : "+f"(c[0]), "+f"(c[1]), "+f"(c[2]), "+f"(c[3])
        : "r"(a[0]), "r"(a[1]), "r"(a[2]), "r"(a[3]), "r"(b[0]), "r"(b[1]));
}

// ---------------------------------------------------------------------------
// Kernel 1: fused  inv_deg[i] = 1/(1 + sum_j adj[i][j])  AND  A_half = fp16(adj)
// ---------------------------------------------------------------------------
__global__ void degconv_kernel(const float* __restrict__ adj) {
    __shared__ float red[256];
    const int row = blockIdx.x;
    const float4* p = reinterpret_cast<const float4*>(adj + (size_t)row * NN);
    uint2* o = reinterpret_cast<uint2*>(g_Ah + (size_t)row * NN);
    float s = 0.f;
#pragma unroll
    for (int i = 0; i < (NN / 4) / 256; i++) {
        const int idx = threadIdx.x + i * 256;
        float4 v = p[idx];
        s += (v.x + v.y) + (v.z + v.w);
        __half2 h0 = __floats2half2_rn(v.x, v.y);
        __half2 h1 = __floats2half2_rn(v.z, v.w);
        uint2 u;
        u.x = *reinterpret_cast<const unsigned*>(&h0);
        u.y = *reinterpret_cast<const unsigned*>(&h1);
        o[idx] = u;
    }
    red[threadIdx.x] = s;
    __syncthreads();
    for (int off = 128; off > 0; off >>= 1) {
        if (threadIdx.x < off) red[threadIdx.x] += red[threadIdx.x + off];
        __syncthreads();
    }
    if (threadIdx.x == 0) g_invdeg[row] = 1.0f / (red[0] + 1.0f);
}

// ---------------------------------------------------------------------------
// Kernel 2: Z = X @ W   (row-major fp32 [8192, 768])
// ---------------------------------------------------------------------------
__global__ void xw_kernel(const float* __restrict__ X, const float* __restrict__ W) {
    __shared__ float Ws[32][33];
    __shared__ float Xs[24][32];
    const int node = blockIdx.x;
    const int tid = threadIdx.x;  // 256
    for (int i = tid; i < 1024; i += 256) Ws[i >> 5][i & 31] = W[i];
    for (int i = tid; i < NCOL; i += 256) Xs[i >> 5][i & 31] = X[(size_t)node * NCOL + i];
    __syncthreads();
    const int o  = tid & 31;
    const int t0 = tid >> 5;
#pragma unroll
    for (int r = 0; r < 3; r++) {
        const int t = t0 + r * 8;
        float acc = 0.f;
#pragma unroll
        for (int a = 0; a < 32; a++) acc += Xs[t][a] * Ws[a][o];
        g_Z[(size_t)node * NCOL + t * 32 + o] = acc;
    }
}

// ---------------------------------------------------------------------------
// Kernel 2b: ZTh = fp16(Z^T)   [768, 8192], K-major B operand
// ---------------------------------------------------------------------------
__global__ void transconv_kernel() {
    __shared__ float s[32][33];
    const int r0 = blockIdx.x * 32;   // node tile
    const int c0 = blockIdx.y * 32;   // feature-col tile
    const int x = threadIdx.x;        // 0..31
    const int y = threadIdx.y;        // 0..7
#pragma unroll
    for (int i = 0; i < 4; i++) {
        const int yy = y + i * 8;
        s[yy][x] = g_Z[(size_t)(r0 + yy) * NCOL + c0 + x];
    }
    __syncthreads();
#pragma unroll
    for (int i = 0; i < 4; i++) {
        const int yy = y + i * 8;
        g_ZTh[(size_t)(c0 + yy) * NN + r0 + x] = __float2half(s[x][yy]);
    }
}

// ---------------------------------------------------------------------------
// Kernel 3: fp16 tensor GEMM   out = (adj @ Z + Z_self) * inv_deg + bias
// CTA tile 128x192, BK=64, 3-stage cp.async, ONE barrier per K-chunk,
// ldmatrix + mma.m16n8k16. 384 threads = 12 warps as 2x6, warp tile 64x32.
// ---------------------------------------------------------------------------
__global__ void __launch_bounds__(THREADS, 1)
gemm_kernel(const float* __restrict__ bias, float* __restrict__ out) {
    extern __shared__ char smem[];
    __shared__ float biasS[32];

    const int tid  = threadIdx.x;
    const int lane = tid & 31;
    const int warp = tid >> 5;
    const int m0 = blockIdx.y * BM;
    const int n0 = blockIdx.x * BN;

    if (tid < 32) biasS[tid] = bias[tid];

    const uint32_t sbase = (uint32_t)__cvta_generic_to_shared(smem);

    // ---- stage loader: 2560 x 16B chunks (A: 1024, B: 1536) ----
    auto load_stage = [&](int kc, int st) {
        const uint32_t Ad = sbase + st * STAGE_BYTES;
        const uint32_t Bd = Ad + A_STAGE_BYTES;
        const __half* Ag = g_Ah  + (size_t)m0 * NN + (size_t)kc * BK;
        const __half* Bg = g_ZTh + (size_t)n0 * NN + (size_t)kc * BK;
#pragma unroll
        for (int i = tid; i < 2560; i += THREADS) {
            if (i < 1024) {
                const int r = i >> 3, c = i & 7;
                cp16(Ad + swz128((uint32_t)(r * 128 + c * 16)),
                     Ag + (size_t)r * NN + c * 8);
            } else {
                const int j = i - 1024;
                const int n = j >> 3, c = j & 7;
                cp16(Bd + swz128((uint32_t)(n * 128 + c * 16)),
                     Bg + (size_t)n * NN + c * 8);
            }
        }
        asm volatile("cp.async.commit_group;\n" ::);
    };

    float acc[4][4][4];
#pragma unroll
    for (int mi = 0; mi < 4; mi++)
#pragma unroll
        for (int ni = 0; ni < 4; ni++)
#pragma unroll
            for (int c = 0; c < 4; c++) acc[mi][ni][c] = 0.f;

    const int wm = (warp / 6) * 64;   // warp M offset
    const int wn = (warp % 6) * 32;   // warp N offset

    const int NKC = NN / BK;  // 128
    load_stage(0, 0);
    load_stage(1, 1);

    for (int kc = 0; kc < NKC; kc++) {
        const int st = kc % STAGES;
        if (kc + 1 < NKC) {
            asm volatile("cp.async.wait_group 1;\n" ::);
        } else {
            asm volatile("cp.async.wait_group 0;\n" ::);
        }
        __syncthreads();
        // Safe single-barrier scheme: stage (kc+2)%STAGES was last READ at
        // iteration kc-1, and every warp has passed the barrier above since.
        if (kc + 2 < NKC) load_stage(kc + 2, (kc + 2) % STAGES);

        const uint32_t Ab = sbase + st * STAGE_BYTES;
        const uint32_t Bb = Ab + A_STAGE_BYTES;
#pragma unroll
        for (int s = 0; s < 4; s++) {        // k16 steps within BK=64
            uint32_t a[4][4];
#pragma unroll
            for (int mi = 0; mi < 4; mi++) {
                const int row = wm + mi * 16 + (lane & 15);
                const uint32_t off = (uint32_t)(row * 128 + s * 32 + (lane >> 4) * 16);
                ldm_x4(a[mi][0], a[mi][1], a[mi][2], a[mi][3], Ab + swz128(off));
            }
            uint32_t b[4][2];
#pragma unroll
            for (int nj = 0; nj < 2; nj++) {
                const int row = wn + nj * 16 + (lane >> 4) * 8 + (lane & 7);
                const uint32_t off = (uint32_t)(row * 128 + s * 32 + ((lane >> 3) & 1) * 16);
                ldm_x4(b[nj * 2][0], b[nj * 2][1], b[nj * 2 + 1][0], b[nj * 2 + 1][1],
                       Bb + swz128(off));
            }
#pragma unroll
            for (int mi = 0; mi < 4; mi++)
#pragma unroll
                for (int ni = 0; ni < 4; ni++)
                    mma_fp16(acc[mi][ni], a[mi], b[ni]);
        }
    }

    // ---- epilogue: (+ self-loop Z) * inv_deg + bias ----
    const int lr = lane >> 2;   // 0..7  (row within m8 group)
    const int lc = lane & 3;    // 0..3  (col pair)
#pragma unroll
    for (int mi = 0; mi < 4; mi++) {
        const int row0 = m0 + wm + mi * 16 + lr;
        const int row1 = row0 + 8;
        const float id0 = g_invdeg[row0];
        const float id1 = g_invdeg[row1];
#pragma unroll
        for (int ni = 0; ni < 4; ni++) {
            const int col = n0 + wn + ni * 8 + lc * 2;
            const float b0v = biasS[col & 31];
            const float b1v = biasS[(col + 1) & 31];
            const float2 z0 = *reinterpret_cast<const float2*>(&g_Z[(size_t)row0 * NCOL + col]);
            const float2 z1 = *reinterpret_cast<const float2*>(&g_Z[(size_t)row1 * NCOL + col]);
            float2 o0, o1;
            o0.x = (acc[mi][ni][0] + z0.x) * id0 + b0v;
            o0.y = (acc[mi][ni][1] + z0.y) * id0 + b1v;
            o1.x = (acc[mi][ni][2] + z1.x) * id1 + b0v;
            o1.y = (acc[mi][ni][3] + z1.y) * id1 + b1v;
            *reinterpret_cast<float2*>(&out[(size_t)row0 * NCOL + col]) = o0;
            *reinterpret_cast<float2*>(&out[(size_t)row1 * NCOL + col]) = o1;
        }
    }
}

// ---------------------------------------------------------------------------
extern "C" void kernel_launch(void* const* d_in, const int* in_sizes, int n_in,
                              void* d_out, int out_size) {
    const float* X    = (const float*)d_in[0];   // node_feats [8192,24,32]
    const float* adj  = (const float*)d_in[1];   // adj_matrix [8192,8192]
    const float* W    = (const float*)d_in[2];   // weight [32,32]
    const float* bias = (const float*)d_in[3];   // bias [32]
    float* out = (float*)d_out;

    cudaFuncSetAttribute(gemm_kernel, cudaFuncAttributeMaxDynamicSharedMemorySize,
                         SMEM_BYTES);

    degconv_kernel<<<NN, 256>>>(adj);
    xw_kernel<<<NN, 256>>>(X, W);
    transconv_kernel<<<dim3(NN / 32, NCOL / 32), dim3(32, 8)>>>();
    gemm_kernel<<<dim3(NCOL / BN, NN / BM), THREADS, SMEM_BYTES>>>(bias, out);
}

// round 5
// speedup vs baseline: 2.0535x; 1.1224x over previous
#include <cuda_runtime.h>
#include <cuda_fp16.h>
#include <cstdint>
#include <cstddef>

#define NN    8192
#define NCOL  768
#define BM    128
#define BN    128
#define BK    64
#define THREADS 256
#define STAGES 3
#define A_STAGE_BYTES (BM * BK * 2)                   // 16384
#define B_STAGE_BYTES (BN * BK * 2)                   // 16384
#define STAGE_BYTES   (A_STAGE_BYTES + B_STAGE_BYTES) // 32768
#define SMEM_BYTES    (STAGES * STAGE_BYTES)          // 98304

// scratch (static device globals: allocation-free per harness rules)
__device__ __half g_Ah [(size_t)NN * NN];     // fp16 adjacency (row-major = K-major)
__device__ float  g_Z  [(size_t)NN * NCOL];   // Z = X@W fp32 (for epilogue self-loop)
__device__ __half g_ZTh[(size_t)NCOL * NN];   // Z^T fp16 (K-major B operand)
__device__ float  g_invdeg[NN];

// ---------------------------------------------------------------------------
// helpers
// ---------------------------------------------------------------------------
__device__ __forceinline__ uint32_t swz128(uint32_t o) { return o ^ ((o >> 3) & 0x70); }

__device__ __forceinline__ void cp16(uint32_t smem_addr, const void* gptr) {
    asm volatile("cp.async.cg.shared.global [%0], [%1], 16;\n"
                 :: "r"(smem_addr), "l"(gptr));
}

__device__ __forceinline__ void ldm_x4(uint32_t& r0, uint32_t& r1, uint32_t& r2,
                                       uint32_t& r3, uint32_t addr) {
    asm volatile("ldmatrix.sync.aligned.m8n8.x4.shared.b16 {%0,%1,%2,%3}, [%4];"
                 : "=r"(r0), "=r"(r1), "=r"(r2), "=r"(r3) : "r"(addr));
}

__device__ __forceinline__ void mma_fp16(float* c, const uint32_t* a, const uint32_t* b) {
    asm volatile(
        "mma.sync.aligned.m16n8k16.row.col.f32.f16.f16.f32 "
        "{%0,%1,%2,%3}, {%4,%5,%6,%7}, {%8,%9}, {%0,%1,%2,%3};\n"
        : "+f"(c[0]), "+f"(c[1]), "+f"(c[2]), "+f"(c[3])
        : "r"(a[0]), "r"(a[1]), "r"(a[2]), "r"(a[3]), "r"(b[0]), "r"(b[1]));
}

// ---------------------------------------------------------------------------
// Kernel 1: fused  inv_deg[i] = 1/(1 + sum_j adj[i][j])  AND  A_half = fp16(adj)
// ---------------------------------------------------------------------------
__global__ void degconv_kernel(const float* __restrict__ adj) {
    __shared__ float red[256];
    const int row = blockIdx.x;
    const float4* p = reinterpret_cast<const float4*>(adj + (size_t)row * NN);
    uint2* o = reinterpret_cast<uint2*>(g_Ah + (size_t)row * NN);
    float s = 0.f;
#pragma unroll
    for (int i = 0; i < (NN / 4) / 256; i++) {
        const int idx = threadIdx.x + i * 256;
        float4 v = p[idx];
        s += (v.x + v.y) + (v.z + v.w);
        __half2 h0 = __floats2half2_rn(v.x, v.y);
        __half2 h1 = __floats2half2_rn(v.z, v.w);
        uint2 u;
        u.x = *reinterpret_cast<const unsigned*>(&h0);
        u.y = *reinterpret_cast<const unsigned*>(&h1);
        o[idx] = u;
    }
    red[threadIdx.x] = s;
    __syncthreads();
    for (int off = 128; off > 0; off >>= 1) {
        if (threadIdx.x < off) red[threadIdx.x] += red[threadIdx.x + off];
        __syncthreads();
    }
    if (threadIdx.x == 0) g_invdeg[row] = 1.0f / (red[0] + 1.0f);
}

// ---------------------------------------------------------------------------
// Kernel 2: Z = X @ W   (row-major fp32 [8192, 768])
// ---------------------------------------------------------------------------
__global__ void xw_kernel(const float* __restrict__ X, const float* __restrict__ W) {
    __shared__ float Ws[32][33];
    __shared__ float Xs[24][32];
    const int node = blockIdx.x;
    const int tid = threadIdx.x;  // 256
    for (int i = tid; i < 1024; i += 256) Ws[i >> 5][i & 31] = W[i];
    for (int i = tid; i < NCOL; i += 256) Xs[i >> 5][i & 31] = X[(size_t)node * NCOL + i];
    __syncthreads();
    const int o  = tid & 31;
    const int t0 = tid >> 5;
#pragma unroll
    for (int r = 0; r < 3; r++) {
        const int t = t0 + r * 8;
        float acc = 0.f;
#pragma unroll
        for (int a = 0; a < 32; a++) acc += Xs[t][a] * Ws[a][o];
        g_Z[(size_t)node * NCOL + t * 32 + o] = acc;
    }
}

// ---------------------------------------------------------------------------
// Kernel 2b: ZTh = fp16(Z^T)   [768, 8192], K-major B operand
// ---------------------------------------------------------------------------
__global__ void transconv_kernel() {
    __shared__ float s[32][33];
    const int r0 = blockIdx.x * 32;   // node tile
    const int c0 = blockIdx.y * 32;   // feature-col tile
    const int x = threadIdx.x;        // 0..31
    const int y = threadIdx.y;        // 0..7
#pragma unroll
    for (int i = 0; i < 4; i++) {
        const int yy = y + i * 8;
        s[yy][x] = g_Z[(size_t)(r0 + yy) * NCOL + c0 + x];
    }
    __syncthreads();
#pragma unroll
    for (int i = 0; i < 4; i++) {
        const int yy = y + i * 8;
        g_ZTh[(size_t)(c0 + yy) * NN + r0 + x] = __float2half(s[x][yy]);
    }
}

// ---------------------------------------------------------------------------
// Kernel 3: fp16 tensor GEMM   out = (adj @ Z + Z_self) * inv_deg + bias
// CTA tile 128x128, BK=64, 3-stage cp.async, one barrier per K-chunk,
// 256 threads = 8 warps as 2x4 (warp tile 64x32), 2 CTAs/SM.
// ---------------------------------------------------------------------------
__global__ void __launch_bounds__(THREADS, 2)
gemm_kernel(const float* __restrict__ bias, float* __restrict__ out) {
    extern __shared__ char smem[];
    __shared__ float biasS[32];

    const int tid  = threadIdx.x;
    const int lane = tid & 31;
    const int warp = tid >> 5;
    const int m0 = blockIdx.y * BM;
    const int n0 = blockIdx.x * BN;

    if (tid < 32) biasS[tid] = bias[tid];

    const uint32_t sbase = (uint32_t)__cvta_generic_to_shared(smem);

    // ---- stage loader: 2048 x 16B chunks (A: 1024, B: 1024) ----
    auto load_stage = [&](int kc, int st) {
        const uint32_t Ad = sbase + st * STAGE_BYTES;
        const uint32_t Bd = Ad + A_STAGE_BYTES;
        const __half* Ag = g_Ah  + (size_t)m0 * NN + (size_t)kc * BK;
        const __half* Bg = g_ZTh + (size_t)n0 * NN + (size_t)kc * BK;
#pragma unroll
        for (int i = tid; i < 2048; i += THREADS) {
            const int r = (i & 1023) >> 3, c = i & 7;
            const uint32_t dst = (i < 1024 ? Ad : Bd) + swz128((uint32_t)(r * 128 + c * 16));
            const __half* src = (i < 1024 ? Ag : Bg) + (size_t)r * NN + c * 8;
            cp16(dst, src);
        }
        asm volatile("cp.async.commit_group;\n" ::);
    };

    float acc[4][4][4];
#pragma unroll
    for (int mi = 0; mi < 4; mi++)
#pragma unroll
        for (int ni = 0; ni < 4; ni++)
#pragma unroll
            for (int c = 0; c < 4; c++) acc[mi][ni][c] = 0.f;

    const int wm = (warp >> 2) * 64;   // warp M offset (2 rows)
    const int wn = (warp & 3) * 32;    // warp N offset (4 cols)

    const int NKC = NN / BK;  // 128
    load_stage(0, 0);
    load_stage(1, 1);

    for (int kc = 0; kc < NKC; kc++) {
        const int st = kc % STAGES;
        if (kc + 1 < NKC) {
            asm volatile("cp.async.wait_group 1;\n" ::);
        } else {
            asm volatile("cp.async.wait_group 0;\n" ::);
        }
        __syncthreads();
        // stage (kc+2)%STAGES was last read at iteration kc-1; all warps have
        // passed the barrier above since, so overwriting it now is race-free.
        if (kc + 2 < NKC) load_stage(kc + 2, (kc + 2) % STAGES);

        const uint32_t Ab = sbase + st * STAGE_BYTES;
        const uint32_t Bb = Ab + A_STAGE_BYTES;
#pragma unroll
        for (int s = 0; s < 4; s++) {        // k16 steps within BK=64
            uint32_t a[4][4];
#pragma unroll
            for (int mi = 0; mi < 4; mi++) {
                const int row = wm + mi * 16 + (lane & 15);
                const uint32_t off = (uint32_t)(row * 128 + s * 32 + (lane >> 4) * 16);
                ldm_x4(a[mi][0], a[mi][1], a[mi][2], a[mi][3], Ab + swz128(off));
            }
            uint32_t b[4][2];
#pragma unroll
            for (int nj = 0; nj < 2; nj++) {
                const int row = wn + nj * 16 + (lane >> 4) * 8 + (lane & 7);
                const uint32_t off = (uint32_t)(row * 128 + s * 32 + ((lane >> 3) & 1) * 16);
                ldm_x4(b[nj * 2][0], b[nj * 2][1], b[nj * 2 + 1][0], b[nj * 2 + 1][1],
                       Bb + swz128(off));
            }
#pragma unroll
            for (int mi = 0; mi < 4; mi++)
#pragma unroll
                for (int ni = 0; ni < 4; ni++)
                    mma_fp16(acc[mi][ni], a[mi], b[ni]);
        }
    }

    // ---- epilogue: (+ self-loop Z) * inv_deg + bias ----
    const int lr = lane >> 2;   // 0..7  (row within m8 group)
    const int lc = lane & 3;    // 0..3  (col pair)
#pragma unroll
    for (int mi = 0; mi < 4; mi++) {
        const int row0 = m0 + wm + mi * 16 + lr;
        const int row1 = row0 + 8;
        const float id0 = g_invdeg[row0];
        const float id1 = g_invdeg[row1];
#pragma unroll
        for (int ni = 0; ni < 4; ni++) {
            const int col = n0 + wn + ni * 8 + lc * 2;
            const float b0v = biasS[col & 31];
            const float b1v = biasS[(col + 1) & 31];
            const float2 z0 = *reinterpret_cast<const float2*>(&g_Z[(size_t)row0 * NCOL + col]);
            const float2 z1 = *reinterpret_cast<const float2*>(&g_Z[(size_t)row1 * NCOL + col]);
            float2 o0, o1;
            o0.x = (acc[mi][ni][0] + z0.x) * id0 + b0v;
            o0.y = (acc[mi][ni][1] + z0.y) * id0 + b1v;
            o1.x = (acc[mi][ni][2] + z1.x) * id1 + b0v;
            o1.y = (acc[mi][ni][3] + z1.y) * id1 + b1v;
            *reinterpret_cast<float2*>(&out[(size_t)row0 * NCOL + col]) = o0;
            *reinterpret_cast<float2*>(&out[(size_t)row1 * NCOL + col]) = o1;
        }
    }
}

// ---------------------------------------------------------------------------
extern "C" void kernel_launch(void* const* d_in, const int* in_sizes, int n_in,
                              void* d_out, int out_size) {
    const float* X    = (const float*)d_in[0];   // node_feats [8192,24,32]
    const float* adj  = (const float*)d_in[1];   // adj_matrix [8192,8192]
    const float* W    = (const float*)d_in[2];   // weight [32,32]
    const float* bias = (const float*)d_in[3];   // bias [32]
    float* out = (float*)d_out;

    cudaFuncSetAttribute(gemm_kernel, cudaFuncAttributeMaxDynamicSharedMemorySize,
                         SMEM_BYTES);

    degconv_kernel<<<NN, 256>>>(adj);
    xw_kernel<<<NN, 256>>>(X, W);
    transconv_kernel<<<dim3(NN / 32, NCOL / 32), dim3(32, 8)>>>();
    gemm_kernel<<<dim3(NCOL / BN, NN / BM), THREADS, SMEM_BYTES>>>(bias, out);
}